// round 10
// baseline (speedup 1.0000x reference)
#include <cuda_runtime.h>

#define TT 35
#define CC 4
#define CIN 7
#define HH 64
#define BN_EPS 1e-5
#define NBS 296         // stats grid: 2 blocks/SM, one wave
#define NCAP 20480      // per-voxel mean scratch capacity

// per-block raw partials: stats 0..9 = P (upper-tri of sum v v^T),
// 10..13 = S (sum v), 14..34 = 21 mean-correction accumulators
__device__ float g_part[35][NBS];
__device__ float4 g_mean[NCAP];        // per-voxel mean of ch0..2 (w unused)
__device__ float g_WpT[CIN * HH];      // BN-folded weights, TRANSPOSED [k][j]
__device__ float g_bp[HH];

// 4-lane-per-voxel moment accumulation: a warp covers 8 voxels at once, each
// lane owning 8-9 rows of its voxel with all loads issued up front (MLP~9).
// Pure moments P/S are mean-free (14 FMA/row); the per-voxel (s,cnt) reduce
// is only 2 shfl levels, once per 8 voxels; corrections are O(1) per voxel
// on the group-leader lane. One 35-value warp reduce per thread-lifetime.
__global__ void __launch_bounds__(256) stats_kernel(const float* __restrict__ vox, int N) {
    const unsigned FULL = 0xffffffffu;
    int lane = threadIdx.x & 31;
    int sl = lane & 3;           // sub-lane within 4-lane group
    int grp = lane >> 2;         // group 0..7 -> voxel within octet
    int wInB = threadIdx.x >> 5;
    int gwarp = blockIdx.x * 8 + wInB;
    int warpsTotal = gridDim.x * 8;
    int nOct = (N + 7) >> 3;

    float accP[10], accS[4], corr[21];
#pragma unroll
    for (int i = 0; i < 10; i++) accP[i] = 0.f;
#pragma unroll
    for (int i = 0; i < 4; i++) accS[i] = 0.f;
#pragma unroll
    for (int i = 0; i < 21; i++) corr[i] = 0.f;

    for (int o = gwarp; o < nOct; o += warpsTotal) {   // 1-2 trips
        int n = o * 8 + grp;
        bool act = (n < N);
        float s0 = 0.f, s1 = 0.f, s2 = 0.f, s3 = 0.f, cnt = 0.f;

        if (act) {
            const float4* vp = (const float4*)vox + (size_t)n * TT;
            float4 buf[9];
#pragma unroll
            for (int i = 0; i < 8; i++) buf[i] = vp[sl + 4 * i];   // rows sl..sl+28
            buf[8] = (sl < TT - 32) ? vp[sl + 32]
                                    : make_float4(0.f, 0.f, 0.f, 0.f);
#pragma unroll
            for (int i = 0; i < 9; i++) {
                float4 v = buf[i];
                s0 += v.x; s1 += v.y; s2 += v.z; s3 += v.w;
                float rs = v.x + v.y + v.z + v.w;
                cnt += (rs != 0.f) ? 1.f : 0.f;
                accP[0] = fmaf(v.x, v.x, accP[0]);
                accP[1] = fmaf(v.y, v.x, accP[1]);
                accP[2] = fmaf(v.y, v.y, accP[2]);
                accP[3] = fmaf(v.z, v.x, accP[3]);
                accP[4] = fmaf(v.z, v.y, accP[4]);
                accP[5] = fmaf(v.z, v.z, accP[5]);
                accP[6] = fmaf(v.w, v.x, accP[6]);
                accP[7] = fmaf(v.w, v.y, accP[7]);
                accP[8] = fmaf(v.w, v.z, accP[8]);
                accP[9] = fmaf(v.w, v.w, accP[9]);
            }
            accS[0] += s0; accS[1] += s1; accS[2] += s2; accS[3] += s3;
        }

        // 2-level group reduce of (s0..s3, cnt) within the 4-lane group
#pragma unroll
        for (int off = 1; off < 4; off <<= 1) {
            s0  += __shfl_xor_sync(FULL, s0, off);
            s1  += __shfl_xor_sync(FULL, s1, off);
            s2  += __shfl_xor_sync(FULL, s2, off);
            s3  += __shfl_xor_sync(FULL, s3, off);
            cnt += __shfl_xor_sync(FULL, cnt, off);
        }

        if (act && sl == 0) {
            float rc = 1.f / cnt;
            float m0 = s0 * rc, m1 = s1 * rc, m2 = s2 * rc;
            if (n < NCAP) g_mean[n] = make_float4(m0, m1, m2, 0.f);
            // cross corrections c = i*4 + l : -m_i * s_l
            corr[0]  -= m0 * s0; corr[1]  -= m0 * s1; corr[2]  -= m0 * s2; corr[3]  -= m0 * s3;
            corr[4]  -= m1 * s0; corr[5]  -= m1 * s1; corr[6]  -= m1 * s2; corr[7]  -= m1 * s3;
            corr[8]  -= m2 * s0; corr[9]  -= m2 * s1; corr[10] -= m2 * s2; corr[11] -= m2 * s3;
            // rel-rel corrections (i>=j): 35 m_i m_j - m_i s_j - m_j s_i
            corr[12] += 35.f * m0 * m0 - 2.f * m0 * s0;
            corr[13] += 35.f * m1 * m0 - m1 * s0 - m0 * s1;
            corr[14] += 35.f * m1 * m1 - 2.f * m1 * s1;
            corr[15] += 35.f * m2 * m0 - m2 * s0 - m0 * s2;
            corr[16] += 35.f * m2 * m1 - m2 * s1 - m1 * s2;
            corr[17] += 35.f * m2 * m2 - 2.f * m2 * s2;
            // S1-rel corrections: -35 m_i
            corr[18] -= 35.f * m0; corr[19] -= 35.f * m1; corr[20] -= 35.f * m2;
        }
    }

    // one uniform 35-value warp reduce per thread-lifetime
    float st[35];
#pragma unroll
    for (int i = 0; i < 10; i++) st[i] = accP[i];
#pragma unroll
    for (int i = 0; i < 4; i++) st[10 + i] = accS[i];
#pragma unroll
    for (int i = 0; i < 21; i++) st[14 + i] = corr[i];   // zero on non-leader lanes
#pragma unroll
    for (int off = 16; off; off >>= 1) {
#pragma unroll
        for (int i = 0; i < 35; i++) st[i] += __shfl_xor_sync(FULL, st[i], off);
    }

    __shared__ float swacc[8][35];
    if (lane == 0) {
#pragma unroll
        for (int i = 0; i < 35; i++) swacc[wInB][i] = st[i];
    }
    __syncthreads();
    if (threadIdx.x < 35) {
        float s = 0.f;
#pragma unroll
        for (int w = 0; w < 8; w++) s += swacc[w][threadIdx.x];
        g_part[threadIdx.x][blockIdx.x] = s;
    }
}

// One block: parallel-reduce partials, map raw pure+corr stats to M/S1 in
// fp64, then fold BN (batch stats from moments) into the linear layer.
__global__ void fold_kernel(const float* __restrict__ Wm, const float* __restrict__ b,
                            const float* __restrict__ gamma, const float* __restrict__ beta,
                            int N) {
    __shared__ float spart[35][8];
    __shared__ double sstat[35];     // assembled M(0..27), S1(28..34)
    __shared__ double sraw[35];
    int tid = threadIdx.x;

    if (tid < 280) {
        int s = tid >> 3;
        int k = tid & 7;
        float acc = 0.f;
        for (int bb = k; bb < NBS; bb += 8) acc += g_part[s][bb];
        spart[s][k] = acc;
    }
    __syncthreads();
    if (tid < 35) {
        double s = 0.0;
#pragma unroll
        for (int k = 0; k < 8; k++) s += (double)spart[tid][k];
        sraw[tid] = s;
    }
    __syncthreads();

    if (tid < 35) {
        // raw layout: 0..9 P, 10..13 S, 14..34 corr
        static const int pureTab[35] = {0,1,2,3,4,5,6,7,8,9,
                                        0,1,3,6, 0, 1,2,4,7, 1,2, 3,4,5,8, 3,4,5,
                                        10,11,12,13, 10,11,12};
        static const int corrTab[35] = {-1,-1,-1,-1,-1,-1,-1,-1,-1,-1,
                                        0,1,2,3, 12, 4,5,6,7, 13,14, 8,9,10,11, 15,16,17,
                                        -1,-1,-1,-1, 18,19,20};
        double v = sraw[pureTab[tid]];
        int c = corrTab[tid];
        if (c >= 0) v += sraw[14 + c];
        sstat[tid] = v;
    }
    __syncthreads();

    int j = tid;
    if (j >= HH) return;

    double M[28], S1[7];
#pragma unroll
    for (int i = 0; i < 28; i++) M[i] = sstat[i];
#pragma unroll
    for (int k = 0; k < 7; k++) S1[k] = sstat[28 + k];

    double w[7];
#pragma unroll
    for (int k = 0; k < 7; k++) w[k] = (double)Wm[j * CIN + k];
    double bj = (double)b[j];

    double dotWS = 0.0;
#pragma unroll
    for (int k = 0; k < 7; k++) dotWS += w[k] * S1[k];

    double quad = 0.0;
    int idx = 0;
#pragma unroll
    for (int k = 0; k < 7; k++) {
#pragma unroll
        for (int l = 0; l <= k; l++) {
            double term = w[k] * w[l] * M[idx];
            quad += (l == k) ? term : 2.0 * term;
            idx++;
        }
    }

    double Nt = (double)N * (double)TT;
    double sumx  = dotWS + Nt * bj;
    double sumxx = quad + 2.0 * bj * dotWS + Nt * bj * bj;
    double mu  = sumx / Nt;
    double var = sumxx / Nt - mu * mu;
    double inv = 1.0 / sqrt(var + (double)BN_EPS);
    double a = (double)gamma[j] * inv;

#pragma unroll
    for (int k = 0; k < 7; k++) g_WpT[k * HH + j] = (float)(a * w[k]);
    g_bp[j] = (float)((double)beta[j] + a * (bj - mu));
}

__device__ __forceinline__ void fma4(float4& v, const float4 w, float a) {
    v.x = fmaf(w.x, a, v.x);
    v.y = fmaf(w.y, a, v.y);
    v.z = fmaf(w.z, a, v.z);
    v.w = fmaf(w.w, a, v.w);
}

// 4 voxels per 256-thread block. Sub-group of 64 threads per voxel; thread
// (g = j&15, tq = j>>4) computes channels 4g..4g+3 for rows t ≡ tq (mod 4)
// with BN-folded weights in registers. Means come precomputed from the stats
// kernel. All output stores are streaming (__stcs) float4.
__global__ __launch_bounds__(256) void main_kernel(const float* __restrict__ vox,
                                                   float* __restrict__ out, int N) {
    __shared__ float4 srow[4 * TT];
    __shared__ float  swpT[CIN][HH];
    __shared__ float  sbp[HH];
    __shared__ float4 spmax[4][4][16];   // [voxel][tq][g]
    __shared__ float4 smaxf[4][16];      // [voxel][g]

    int tid = threadIdx.x;
    int base = blockIdx.x * 4;

    if (tid < HH) {
#pragma unroll
        for (int k = 0; k < CIN; k++) swpT[k][tid] = g_WpT[k * HH + tid];
        sbp[tid] = g_bp[tid];
    }
    {
        int nv4 = min(4, N - base) * TT;
        if (tid < nv4)
            srow[tid] = ((const float4*)(vox + (size_t)base * (TT * CC)))[tid];
    }
    __syncthreads();

    int sub = tid >> 6;
    int j = tid & 63;
    int g = j & 15, tq = j >> 4;
    int n = base + sub;
    bool active = (n < N);

    float4 pmax = make_float4(0.f, 0.f, 0.f, 0.f);   // ReLU output >= 0
    float* ob = out + (size_t)n * (TT * 2 * HH) + g * 4;

    if (active) {
        float4 w0 = *(const float4*)&swpT[0][g * 4];
        float4 w1 = *(const float4*)&swpT[1][g * 4];
        float4 w2 = *(const float4*)&swpT[2][g * 4];
        float4 w3 = *(const float4*)&swpT[3][g * 4];
        float4 w4 = *(const float4*)&swpT[4][g * 4];
        float4 w5 = *(const float4*)&swpT[5][g * 4];
        float4 w6 = *(const float4*)&swpT[6][g * 4];
        float4 bias = *(const float4*)&sbp[g * 4];

        float mx, my, mz;
        if (n < NCAP) {
            float4 m = g_mean[n];
            mx = m.x; my = m.y; mz = m.z;
        } else {
            float sx = 0.f, sy = 0.f, sz = 0.f, cnt = 0.f;
            for (int t = 0; t < TT; t++) {
                float4 r = srow[sub * TT + t];
                sx += r.x; sy += r.y; sz += r.z;
                if (r.x + r.y + r.z + r.w != 0.f) cnt += 1.f;
            }
            float inv = 1.f / cnt;
            mx = sx * inv; my = sy * inv; mz = sz * inv;
        }

        const float4* sr = &srow[sub * TT];
#pragma unroll
        for (int i = 0; i < 9; i++) {
            int t = tq + i * 4;
            if (t < TT) {
                float4 r = sr[t];
                float4 v = bias;
                fma4(v, w0, r.x);
                fma4(v, w1, r.y);
                fma4(v, w2, r.z);
                fma4(v, w3, r.w);
                fma4(v, w4, r.x - mx);
                fma4(v, w5, r.y - my);
                fma4(v, w6, r.z - mz);
                v.x = fmaxf(v.x, 0.f); v.y = fmaxf(v.y, 0.f);
                v.z = fmaxf(v.z, 0.f); v.w = fmaxf(v.w, 0.f);
                pmax.x = fmaxf(pmax.x, v.x); pmax.y = fmaxf(pmax.y, v.y);
                pmax.z = fmaxf(pmax.z, v.z); pmax.w = fmaxf(pmax.w, v.w);
                __stcs((float4*)(ob + t * (2 * HH)), v);
            }
        }
    }
    spmax[sub][tq][g] = pmax;
    __syncthreads();

    if (tid < 64) {
        int s2 = tid >> 4, g2 = tid & 15;
        float4 a = spmax[s2][0][g2], b2 = spmax[s2][1][g2];
        float4 c = spmax[s2][2][g2], d = spmax[s2][3][g2];
        float4 m;
        m.x = fmaxf(fmaxf(a.x, b2.x), fmaxf(c.x, d.x));
        m.y = fmaxf(fmaxf(a.y, b2.y), fmaxf(c.y, d.y));
        m.z = fmaxf(fmaxf(a.z, b2.z), fmaxf(c.z, d.z));
        m.w = fmaxf(fmaxf(a.w, b2.w), fmaxf(c.w, d.w));
        smaxf[s2][g2] = m;
    }
    __syncthreads();

    if (active) {
        float4 mv = smaxf[sub][g];
        float* obm = ob + HH;
#pragma unroll
        for (int i = 0; i < 9; i++) {
            int t = tq + i * 4;
            if (t < TT) __stcs((float4*)(obm + t * (2 * HH)), mv);
        }
    }
}

extern "C" void kernel_launch(void* const* d_in, const int* in_sizes, int n_in,
                              void* d_out, int out_size) {
    const float* vox   = (const float*)d_in[0];
    const float* Wm    = (const float*)d_in[1];
    const float* b     = (const float*)d_in[2];
    const float* gamma = (const float*)d_in[3];
    const float* beta  = (const float*)d_in[4];
    float* out = (float*)d_out;

    int N = in_sizes[0] / (TT * CC);

    stats_kernel<<<NBS, 256>>>(vox, N);
    fold_kernel<<<1, 288>>>(Wm, b, gamma, beta, N);
    main_kernel<<<(N + 3) / 4, 256>>>(vox, out, N);
}

// round 11
// speedup vs baseline: 1.0005x; 1.0005x over previous
#include <cuda_runtime.h>

#define TT 35
#define CC 4
#define CIN 7
#define HH 64
#define BN_EPS 1e-5
#define VPB 64          // voxels per stats block
#define NBMAX 320       // max stats blocks (N <= 20480)
#define NCAP 20480      // per-voxel mean scratch capacity

// per-block raw partials: stats 0..9 = P (upper-tri of sum v v^T),
// 10..13 = S (sum v), 14..34 = 21 mean-correction accumulators
__device__ float g_part[35][NBMAX];
__device__ float4 g_mean[NCAP];        // per-voxel mean of ch0..2 (w unused)
__device__ float g_WpT[CIN * HH];      // BN-folded weights, TRANSPOSED [k][j]
__device__ float g_bp[HH];

// TMA-staged stats: one cp.async.bulk per block copies 64 voxels (35840 B)
// into smem at streaming bandwidth (no per-thread MLP limit), then a thread
// pair per voxel accumulates the mean-free moments from smem. One shfl level
// merges the pair; corrections are O(1) per voxel on the even lane. The only
// wide reduction is one 35-value warp+block reduce at thread exit.
__global__ void __launch_bounds__(128) stats_kernel(const float* __restrict__ vox, int N) {
    __shared__ __align__(128) float4 sdata[VPB * TT];          // 35840 B
    __shared__ __align__(8) unsigned long long smbar;
    __shared__ float swacc[4][35];

    const unsigned FULL = 0xffffffffu;
    int tid = threadIdx.x;
    int lane = tid & 31;
    int w = tid >> 5;
    int base = blockIdx.x * VPB;
    int nv = min(VPB, N - base);
    unsigned bytes = (unsigned)nv * (TT * CC * 4);

    unsigned mbar = (unsigned)__cvta_generic_to_shared(&smbar);
    unsigned sdst = (unsigned)__cvta_generic_to_shared(sdata);

    if (tid == 0)
        asm volatile("mbarrier.init.shared.b64 [%0], 1;" :: "r"(mbar) : "memory");
    __syncthreads();
    if (tid == 0) {
        asm volatile("mbarrier.arrive.expect_tx.shared.b64 _, [%0], %1;"
                     :: "r"(mbar), "r"(bytes) : "memory");
        asm volatile("cp.async.bulk.shared::cta.global.mbarrier::complete_tx::bytes "
                     "[%0], [%1], %2, [%3];"
                     :: "r"(sdst), "l"(vox + (size_t)base * (TT * CC)),
                        "r"(bytes), "r"(mbar) : "memory");
    }
    // every thread waits for the bulk copy (phase 0)
    {
        unsigned done = 0;
        while (!done) {
            asm volatile(
                "{\n\t.reg .pred p;\n\t"
                "mbarrier.try_wait.parity.shared.b64 p, [%1], %2, 0x989680;\n\t"
                "selp.b32 %0, 1, 0, p;\n\t}"
                : "=r"(done) : "r"(mbar), "r"(0u) : "memory");
        }
    }

    float accP[10], accS[4], corr[21];
#pragma unroll
    for (int i = 0; i < 10; i++) accP[i] = 0.f;
#pragma unroll
    for (int i = 0; i < 4; i++) accS[i] = 0.f;
#pragma unroll
    for (int i = 0; i < 21; i++) corr[i] = 0.f;

    int v0 = tid >> 1;           // voxel within block
    int sub = tid & 1;           // half: rows 0-17 / 18-34
    int n = base + v0;
    bool act = (v0 < nv);

    float s0 = 0.f, s1 = 0.f, s2 = 0.f, s3 = 0.f, cnt = 0.f;
    if (act) {
        const float4* vp = sdata + v0 * TT;
        int r0 = sub * 18;
        int nRows = 18 - sub;    // 18 for sub0, 17 for sub1
#pragma unroll
        for (int i = 0; i < 18; i++) {
            if (i < nRows) {
                float4 v = vp[r0 + i];
                s0 += v.x; s1 += v.y; s2 += v.z; s3 += v.w;
                float rs = v.x + v.y + v.z + v.w;
                cnt += (rs != 0.f) ? 1.f : 0.f;
                accP[0] = fmaf(v.x, v.x, accP[0]);
                accP[1] = fmaf(v.y, v.x, accP[1]);
                accP[2] = fmaf(v.y, v.y, accP[2]);
                accP[3] = fmaf(v.z, v.x, accP[3]);
                accP[4] = fmaf(v.z, v.y, accP[4]);
                accP[5] = fmaf(v.z, v.z, accP[5]);
                accP[6] = fmaf(v.w, v.x, accP[6]);
                accP[7] = fmaf(v.w, v.y, accP[7]);
                accP[8] = fmaf(v.w, v.z, accP[8]);
                accP[9] = fmaf(v.w, v.w, accP[9]);
            }
        }
        accS[0] += s0; accS[1] += s1; accS[2] += s2; accS[3] += s3;
    }

    // merge the thread pair (lanes tid, tid^1): one shfl level
    s0  += __shfl_xor_sync(FULL, s0, 1);
    s1  += __shfl_xor_sync(FULL, s1, 1);
    s2  += __shfl_xor_sync(FULL, s2, 1);
    s3  += __shfl_xor_sync(FULL, s3, 1);
    cnt += __shfl_xor_sync(FULL, cnt, 1);

    if (act && sub == 0) {
        float rc = 1.f / cnt;
        float m0 = s0 * rc, m1 = s1 * rc, m2 = s2 * rc;
        if (n < NCAP) g_mean[n] = make_float4(m0, m1, m2, 0.f);
        // cross corrections c = i*4 + l : -m_i * s_l
        corr[0]  = -m0 * s0; corr[1]  = -m0 * s1; corr[2]  = -m0 * s2; corr[3]  = -m0 * s3;
        corr[4]  = -m1 * s0; corr[5]  = -m1 * s1; corr[6]  = -m1 * s2; corr[7]  = -m1 * s3;
        corr[8]  = -m2 * s0; corr[9]  = -m2 * s1; corr[10] = -m2 * s2; corr[11] = -m2 * s3;
        // rel-rel corrections (i>=j): 35 m_i m_j - m_i s_j - m_j s_i
        corr[12] = 35.f * m0 * m0 - 2.f * m0 * s0;
        corr[13] = 35.f * m1 * m0 - m1 * s0 - m0 * s1;
        corr[14] = 35.f * m1 * m1 - 2.f * m1 * s1;
        corr[15] = 35.f * m2 * m0 - m2 * s0 - m0 * s2;
        corr[16] = 35.f * m2 * m1 - m2 * s1 - m1 * s2;
        corr[17] = 35.f * m2 * m2 - 2.f * m2 * s2;
        // S1-rel corrections: -35 m_i
        corr[18] = -35.f * m0; corr[19] = -35.f * m1; corr[20] = -35.f * m2;
    }

    // one uniform 35-value warp reduce per thread-lifetime
    float st[35];
#pragma unroll
    for (int i = 0; i < 10; i++) st[i] = accP[i];
#pragma unroll
    for (int i = 0; i < 4; i++) st[10 + i] = accS[i];
#pragma unroll
    for (int i = 0; i < 21; i++) st[14 + i] = corr[i];   // zero on non-leader lanes
#pragma unroll
    for (int off = 16; off; off >>= 1) {
#pragma unroll
        for (int i = 0; i < 35; i++) st[i] += __shfl_xor_sync(FULL, st[i], off);
    }

    if (lane == 0) {
#pragma unroll
        for (int i = 0; i < 35; i++) swacc[w][i] = st[i];
    }
    __syncthreads();
    if (tid < 35) {
        float s = swacc[0][tid] + swacc[1][tid] + swacc[2][tid] + swacc[3][tid];
        g_part[tid][blockIdx.x] = s;
    }
}

// One block: parallel-reduce partials, map raw pure+corr stats to M/S1 in
// fp64, then fold BN (batch stats from moments) into the linear layer.
__global__ void fold_kernel(const float* __restrict__ Wm, const float* __restrict__ b,
                            const float* __restrict__ gamma, const float* __restrict__ beta,
                            int N, int nb) {
    __shared__ float spart[35][8];
    __shared__ double sstat[35];     // assembled M(0..27), S1(28..34)
    __shared__ double sraw[35];
    int tid = threadIdx.x;

    if (tid < 280) {
        int s = tid >> 3;
        int k = tid & 7;
        float acc = 0.f;
        for (int bb = k; bb < nb; bb += 8) acc += g_part[s][bb];
        spart[s][k] = acc;
    }
    __syncthreads();
    if (tid < 35) {
        double s = 0.0;
#pragma unroll
        for (int k = 0; k < 8; k++) s += (double)spart[tid][k];
        sraw[tid] = s;
    }
    __syncthreads();

    if (tid < 35) {
        // raw layout: 0..9 P, 10..13 S, 14..34 corr
        static const int pureTab[35] = {0,1,2,3,4,5,6,7,8,9,
                                        0,1,3,6, 0, 1,2,4,7, 1,2, 3,4,5,8, 3,4,5,
                                        10,11,12,13, 10,11,12};
        static const int corrTab[35] = {-1,-1,-1,-1,-1,-1,-1,-1,-1,-1,
                                        0,1,2,3, 12, 4,5,6,7, 13,14, 8,9,10,11, 15,16,17,
                                        -1,-1,-1,-1, 18,19,20};
        double v = sraw[pureTab[tid]];
        int c = corrTab[tid];
        if (c >= 0) v += sraw[14 + c];
        sstat[tid] = v;
    }
    __syncthreads();

    int j = tid;
    if (j >= HH) return;

    double M[28], S1[7];
#pragma unroll
    for (int i = 0; i < 28; i++) M[i] = sstat[i];
#pragma unroll
    for (int k = 0; k < 7; k++) S1[k] = sstat[28 + k];

    double w[7];
#pragma unroll
    for (int k = 0; k < 7; k++) w[k] = (double)Wm[j * CIN + k];
    double bj = (double)b[j];

    double dotWS = 0.0;
#pragma unroll
    for (int k = 0; k < 7; k++) dotWS += w[k] * S1[k];

    double quad = 0.0;
    int idx = 0;
#pragma unroll
    for (int k = 0; k < 7; k++) {
#pragma unroll
        for (int l = 0; l <= k; l++) {
            double term = w[k] * w[l] * M[idx];
            quad += (l == k) ? term : 2.0 * term;
            idx++;
        }
    }

    double Nt = (double)N * (double)TT;
    double sumx  = dotWS + Nt * bj;
    double sumxx = quad + 2.0 * bj * dotWS + Nt * bj * bj;
    double mu  = sumx / Nt;
    double var = sumxx / Nt - mu * mu;
    double inv = 1.0 / sqrt(var + (double)BN_EPS);
    double a = (double)gamma[j] * inv;

#pragma unroll
    for (int k = 0; k < 7; k++) g_WpT[k * HH + j] = (float)(a * w[k]);
    g_bp[j] = (float)((double)beta[j] + a * (bj - mu));
}

__device__ __forceinline__ void fma4(float4& v, const float4 w, float a) {
    v.x = fmaf(w.x, a, v.x);
    v.y = fmaf(w.y, a, v.y);
    v.z = fmaf(w.z, a, v.z);
    v.w = fmaf(w.w, a, v.w);
}

// 4 voxels per 256-thread block. Sub-group of 64 threads per voxel; thread
// (g = j&15, tq = j>>4) computes channels 4g..4g+3 for rows t ≡ tq (mod 4)
// with BN-folded weights in registers. Means come precomputed from the stats
// kernel. All output stores are streaming (__stcs) float4.
__global__ __launch_bounds__(256) void main_kernel(const float* __restrict__ vox,
                                                   float* __restrict__ out, int N) {
    __shared__ float4 srow[4 * TT];
    __shared__ float  swpT[CIN][HH];
    __shared__ float  sbp[HH];
    __shared__ float4 spmax[4][4][16];   // [voxel][tq][g]
    __shared__ float4 smaxf[4][16];      // [voxel][g]

    int tid = threadIdx.x;
    int base = blockIdx.x * 4;

    if (tid < HH) {
#pragma unroll
        for (int k = 0; k < CIN; k++) swpT[k][tid] = g_WpT[k * HH + tid];
        sbp[tid] = g_bp[tid];
    }
    {
        int nv4 = min(4, N - base) * TT;
        if (tid < nv4)
            srow[tid] = ((const float4*)(vox + (size_t)base * (TT * CC)))[tid];
    }
    __syncthreads();

    int sub = tid >> 6;
    int j = tid & 63;
    int g = j & 15, tq = j >> 4;
    int n = base + sub;
    bool active = (n < N);

    float4 pmax = make_float4(0.f, 0.f, 0.f, 0.f);   // ReLU output >= 0
    float* ob = out + (size_t)n * (TT * 2 * HH) + g * 4;

    if (active) {
        float4 w0 = *(const float4*)&swpT[0][g * 4];
        float4 w1 = *(const float4*)&swpT[1][g * 4];
        float4 w2 = *(const float4*)&swpT[2][g * 4];
        float4 w3 = *(const float4*)&swpT[3][g * 4];
        float4 w4 = *(const float4*)&swpT[4][g * 4];
        float4 w5 = *(const float4*)&swpT[5][g * 4];
        float4 w6 = *(const float4*)&swpT[6][g * 4];
        float4 bias = *(const float4*)&sbp[g * 4];

        float mx, my, mz;
        if (n < NCAP) {
            float4 m = g_mean[n];
            mx = m.x; my = m.y; mz = m.z;
        } else {
            float sx = 0.f, sy = 0.f, sz = 0.f, cnt = 0.f;
            for (int t = 0; t < TT; t++) {
                float4 r = srow[sub * TT + t];
                sx += r.x; sy += r.y; sz += r.z;
                if (r.x + r.y + r.z + r.w != 0.f) cnt += 1.f;
            }
            float inv = 1.f / cnt;
            mx = sx * inv; my = sy * inv; mz = sz * inv;
        }

        const float4* sr = &srow[sub * TT];
#pragma unroll
        for (int i = 0; i < 9; i++) {
            int t = tq + i * 4;
            if (t < TT) {
                float4 r = sr[t];
                float4 v = bias;
                fma4(v, w0, r.x);
                fma4(v, w1, r.y);
                fma4(v, w2, r.z);
                fma4(v, w3, r.w);
                fma4(v, w4, r.x - mx);
                fma4(v, w5, r.y - my);
                fma4(v, w6, r.z - mz);
                v.x = fmaxf(v.x, 0.f); v.y = fmaxf(v.y, 0.f);
                v.z = fmaxf(v.z, 0.f); v.w = fmaxf(v.w, 0.f);
                pmax.x = fmaxf(pmax.x, v.x); pmax.y = fmaxf(pmax.y, v.y);
                pmax.z = fmaxf(pmax.z, v.z); pmax.w = fmaxf(pmax.w, v.w);
                __stcs((float4*)(ob + t * (2 * HH)), v);
            }
        }
    }
    spmax[sub][tq][g] = pmax;
    __syncthreads();

    if (tid < 64) {
        int s2 = tid >> 4, g2 = tid & 15;
        float4 a = spmax[s2][0][g2], b2 = spmax[s2][1][g2];
        float4 c = spmax[s2][2][g2], d = spmax[s2][3][g2];
        float4 m;
        m.x = fmaxf(fmaxf(a.x, b2.x), fmaxf(c.x, d.x));
        m.y = fmaxf(fmaxf(a.y, b2.y), fmaxf(c.y, d.y));
        m.z = fmaxf(fmaxf(a.z, b2.z), fmaxf(c.z, d.z));
        m.w = fmaxf(fmaxf(a.w, b2.w), fmaxf(c.w, d.w));
        smaxf[s2][g2] = m;
    }
    __syncthreads();

    if (active) {
        float4 mv = smaxf[sub][g];
        float* obm = ob + HH;
#pragma unroll
        for (int i = 0; i < 9; i++) {
            int t = tq + i * 4;
            if (t < TT) __stcs((float4*)(obm + t * (2 * HH)), mv);
        }
    }
}

extern "C" void kernel_launch(void* const* d_in, const int* in_sizes, int n_in,
                              void* d_out, int out_size) {
    const float* vox   = (const float*)d_in[0];
    const float* Wm    = (const float*)d_in[1];
    const float* b     = (const float*)d_in[2];
    const float* gamma = (const float*)d_in[3];
    const float* beta  = (const float*)d_in[4];
    float* out = (float*)d_out;

    int N = in_sizes[0] / (TT * CC);
    int nbStats = (N + VPB - 1) / VPB;
    if (nbStats > NBMAX) nbStats = NBMAX;   // (N <= 20480 for this problem)

    stats_kernel<<<nbStats, 128>>>(vox, N);
    fold_kernel<<<1, 288>>>(Wm, b, gamma, beta, N, nbStats);
    main_kernel<<<(N + 3) / 4, 256>>>(vox, out, N);
}